// round 2
// baseline (speedup 1.0000x reference)
#include <cuda_runtime.h>
#include <cuda_bf16.h>
#include <cstdint>

// Problem constants
#define BB   2
#define NN   10000
#define EE   100000
#define FF   512
#define HH   512
#define MROWS (BB*NN)        // 20000 rows into the node GEMM
#define NTOT  (2*HH)         // 1024 cols: [W1 | W2]
#define NEDGE (BB*EE)        // 200000 directed edge slots
#define NSEG  (BB*NN)        // 20000 segments per direction

// ---------------- scratch (static device globals; no allocation) -------------
__device__ float          g_pre[(size_t)MROWS * NTOT];     // 82 MB: X@[W1|W2]
__device__ __nv_bfloat16  g_A1[(size_t)MROWS * HH];        // 20.5 MB
__device__ __nv_bfloat16  g_A2[(size_t)MROWS * HH];        // 20.5 MB
__device__ float          g_eij[NEDGE];
__device__ float          g_eji[NEDGE];
__device__ float          g_sums[2 * NSEG];                // [src sums | dst sums]

// ---------------- kernel 0: zero segment sums --------------------------------
__global__ void zero_sums_kernel() {
    int i = blockIdx.x * blockDim.x + threadIdx.x;
    if (i < 2 * NSEG) g_sums[i] = 0.0f;
}

// ---------------- kernel 1: SGEMM  X(20000x512) @ [W1|W2](512x1024) ----------
__global__ __launch_bounds__(256) void sgemm_kernel(
    const float* __restrict__ X,
    const float* __restrict__ W1,
    const float* __restrict__ W2)
{
    const int BM = 128, BK = 16;
    __shared__ float As[16][128 + 4];
    __shared__ float Bs[16][128];

    int m0 = blockIdx.y * BM;
    int n0 = blockIdx.x * 128;
    const float* Wp = (n0 < HH) ? W1 : W2;
    int ncol0 = n0 & (HH - 1);

    int tid = threadIdx.x;
    int ty = tid >> 4;       // 0..15
    int tx = tid & 15;       // 0..15

    float acc[8][8];
#pragma unroll
    for (int i = 0; i < 8; i++)
#pragma unroll
        for (int j = 0; j < 8; j++) acc[i][j] = 0.0f;

    for (int k0 = 0; k0 < FF; k0 += BK) {
        // Load A tile: 128 rows x 16 cols = 512 float4
#pragma unroll
        for (int r = 0; r < 2; r++) {
            int f   = tid + r * 256;
            int row = f >> 2;      // 0..127
            int c4  = f & 3;       // 0..3
            float4 v = make_float4(0.f, 0.f, 0.f, 0.f);
            int gm = m0 + row;
            if (gm < MROWS)
                v = *(const float4*)(X + (size_t)gm * FF + k0 + c4 * 4);
            As[c4 * 4 + 0][row] = v.x;
            As[c4 * 4 + 1][row] = v.y;
            As[c4 * 4 + 2][row] = v.z;
            As[c4 * 4 + 3][row] = v.w;
        }
        // Load B tile: 16 rows x 128 cols = 512 float4
#pragma unroll
        for (int r = 0; r < 2; r++) {
            int f   = tid + r * 256;
            int row = f >> 5;      // 0..15
            int c4  = f & 31;      // 0..31
            float4 v = *(const float4*)(Wp + (size_t)(k0 + row) * HH + ncol0 + c4 * 4);
            *(float4*)(&Bs[row][c4 * 4]) = v;
        }
        __syncthreads();

#pragma unroll
        for (int k = 0; k < BK; k++) {
            float a[8], b[8];
#pragma unroll
            for (int i = 0; i < 8; i++) a[i] = As[k][ty * 8 + i];
#pragma unroll
            for (int j = 0; j < 8; j++) b[j] = Bs[k][tx * 8 + j];
#pragma unroll
            for (int i = 0; i < 8; i++)
#pragma unroll
                for (int j = 0; j < 8; j++)
                    acc[i][j] = fmaf(a[i], b[j], acc[i][j]);
        }
        __syncthreads();
    }

#pragma unroll
    for (int i = 0; i < 8; i++) {
        int gm = m0 + ty * 8 + i;
        if (gm < MROWS) {
            float* o = g_pre + (size_t)gm * NTOT + n0 + tx * 8;
            *(float4*)(o)     = make_float4(acc[i][0], acc[i][1], acc[i][2], acc[i][3]);
            *(float4*)(o + 4) = make_float4(acc[i][4], acc[i][5], acc[i][6], acc[i][7]);
        }
    }
}

// ---------------- kernel 2: LayerNorm per row-half, write bf16 ---------------
__global__ __launch_bounds__(256) void ln_kernel(
    const float* __restrict__ b1, const float* __restrict__ g1, const float* __restrict__ bb1,
    const float* __restrict__ b2, const float* __restrict__ g2, const float* __restrict__ bb2)
{
    int row  = blockIdx.x;          // 0..19999
    int half = blockIdx.y;          // 0: W1 path, 1: W2 path
    const float* p   = g_pre + (size_t)row * NTOT + half * HH;
    const float* bv  = half ? b2  : b1;
    const float* gv  = half ? g2  : g1;
    const float* bbv = half ? bb2 : bb1;

    int t = threadIdx.x;
    float v0 = p[t]       + bv[t];
    float v1 = p[t + 256] + bv[t + 256];

    float s  = v0 + v1;
    float sq = v0 * v0 + v1 * v1;
#pragma unroll
    for (int o = 16; o; o >>= 1) {
        s  += __shfl_xor_sync(0xffffffffu, s,  o);
        sq += __shfl_xor_sync(0xffffffffu, sq, o);
    }
    __shared__ float red[2][8];
    int w = t >> 5, l = t & 31;
    if (l == 0) { red[0][w] = s; red[1][w] = sq; }
    __syncthreads();
    float S = 0.f, SQ = 0.f;
#pragma unroll
    for (int i = 0; i < 8; i++) { S += red[0][i]; SQ += red[1][i]; }

    float mu  = S * (1.0f / HH);
    float var = SQ * (1.0f / HH) - mu * mu;
    float rs  = rsqrtf(var + 1e-5f);

    __nv_bfloat16* Aout = (half ? g_A2 : g_A1) + (size_t)row * HH;
    Aout[t]       = __float2bfloat16((v0 - mu) * rs * gv[t]       + bbv[t]);
    Aout[t + 256] = __float2bfloat16((v1 - mu) * rs * gv[t + 256] + bbv[t + 256]);
}

// ---------------- kernel 3: warp-per-edge scoring + segment sums -------------
__device__ __forceinline__ void bf8_to_f(uint4 u, float* f) {
    const __nv_bfloat162* p = (const __nv_bfloat162*)&u;
#pragma unroll
    for (int i = 0; i < 4; i++) {
        float2 t = __bfloat1622float2(p[i]);
        f[2 * i]     = t.x;
        f[2 * i + 1] = t.y;
    }
}

__global__ __launch_bounds__(256) void edge_kernel(
    const int* __restrict__ ei,
    const float* __restrict__ W3,
    const float* __restrict__ W4,
    const float* __restrict__ b4)
{
    int gw   = (blockIdx.x * 256 + threadIdx.x) >> 5;
    int lane = threadIdx.x & 31;
    if (gw >= NEDGE) return;
    int b = gw / EE;
    int e = gw - b * EE;

    int src = ei[(size_t)b * 2 * EE + e];
    int dst = ei[(size_t)b * 2 * EE + EE + e];

    const __nv_bfloat16* a1s = g_A1 + ((size_t)b * NN + src) * HH;
    const __nv_bfloat16* a2s = g_A2 + ((size_t)b * NN + src) * HH;
    const __nv_bfloat16* a1d = g_A1 + ((size_t)b * NN + dst) * HH;
    const __nv_bfloat16* a2d = g_A2 + ((size_t)b * NN + dst) * HH;

    float s1 = 0.f, s2 = 0.f;
#pragma unroll
    for (int i = 0; i < 2; i++) {
        int off = (i * 32 + lane) * 8;
        float x1s[8], x2s[8], x1d[8], x2d[8];
        bf8_to_f(*(const uint4*)(a1s + off), x1s);
        bf8_to_f(*(const uint4*)(a2d + off), x2d);
        bf8_to_f(*(const uint4*)(a1d + off), x1d);
        bf8_to_f(*(const uint4*)(a2s + off), x2s);
        float4 wa = *(const float4*)(W3 + off);
        float4 wb = *(const float4*)(W3 + off + 4);
        float w[8] = {wa.x, wa.y, wa.z, wa.w, wb.x, wb.y, wb.z, wb.w};
#pragma unroll
        for (int j = 0; j < 8; j++) {
            s1 = fmaf(fmaxf(x1s[j] + x2d[j], 0.f), w[j], s1);
            s2 = fmaf(fmaxf(x1d[j] + x2s[j], 0.f), w[j], s2);
        }
    }
#pragma unroll
    for (int o = 16; o; o >>= 1) {
        s1 += __shfl_xor_sync(0xffffffffu, s1, o);
        s2 += __shfl_xor_sync(0xffffffffu, s2, o);
    }
    if (lane == 0) {
        float d  = s1 - s2;                 // b3 cancels in Zij - Zji
        float w4 = W4[0], bb = b4[0];
        float vij = fmaxf(fmaf( d, w4, bb), 0.f);
        float vji = fmaxf(fmaf(-d, w4, bb), 0.f);
        float pi = expf(vij);               // max-subtraction removable: exact ratio
        float pj = expf(vji);
        g_eij[(size_t)b * EE + e] = pi;
        g_eji[(size_t)b * EE + e] = pj;
        atomicAdd(&g_sums[b * NN + src], pi);
        atomicAdd(&g_sums[NSEG + b * NN + dst], pj);
    }
}

// ---------------- kernel 4: normalize + write output -------------------------
__global__ __launch_bounds__(256) void norm_kernel(
    const int* __restrict__ ei,
    float* __restrict__ out)
{
    int i = blockIdx.x * 256 + threadIdx.x;
    if (i >= NEDGE) return;
    int b = i / EE;
    int e = i - b * EE;
    int src = ei[(size_t)b * 2 * EE + e];
    int dst = ei[(size_t)b * 2 * EE + EE + e];
    out[i]         = g_eij[i] / g_sums[b * NN + src];
    out[NEDGE + i] = g_eji[i] / g_sums[NSEG + b * NN + dst];
}

// ---------------- launcher ---------------------------------------------------
extern "C" void kernel_launch(void* const* d_in, const int* in_sizes, int n_in,
                              void* d_out, int out_size)
{
    int idx = 0;
    const float* X  = (const float*)d_in[idx++];   // node_features, 10,240,000
    const int*   EI = (const int*)  d_in[idx++];   // edge_index,       400,000
    if (idx < n_in && in_sizes[idx] == 1) idx++;   // num_nodes scalar (if present)
    const float* W1  = (const float*)d_in[idx++];  // 262144
    const float* b1  = (const float*)d_in[idx++];  // 512
    const float* g1  = (const float*)d_in[idx++];  // 512
    const float* bb1 = (const float*)d_in[idx++];  // 512
    const float* W2  = (const float*)d_in[idx++];  // 262144
    const float* b2  = (const float*)d_in[idx++];  // 512
    const float* g2  = (const float*)d_in[idx++];  // 512
    const float* bb2 = (const float*)d_in[idx++];  // 512
    const float* W3  = (const float*)d_in[idx++];  // 512
    idx++;                                          // b3 (cancels)
    const float* W4  = (const float*)d_in[idx++];  // 1
    const float* b4  = (const float*)d_in[idx++];  // 1

    float* out = (float*)d_out;

    zero_sums_kernel<<<(2 * NSEG + 255) / 256, 256>>>();

    dim3 ggrid(NTOT / 128, (MROWS + 127) / 128);
    sgemm_kernel<<<ggrid, 256>>>(X, W1, W2);

    dim3 lgrid(MROWS, 2);
    ln_kernel<<<lgrid, 256>>>(b1, g1, bb1, b2, g2, bb2);

    int edge_blocks = (NEDGE * 32 + 255) / 256;
    edge_kernel<<<edge_blocks, 256>>>(EI, W3, W4, b4);

    norm_kernel<<<(NEDGE + 255) / 256, 256>>>(EI, out);
}

// round 4
// speedup vs baseline: 2.7547x; 2.7547x over previous
#include <cuda_runtime.h>
#include <cuda_bf16.h>
#include <cstdint>

// Problem constants
#define BB   2
#define NN   10000
#define EE   100000
#define FF   512
#define HH   512
#define MROWS (BB*NN)        // 20000 rows into the node GEMM
#define NTOT  (2*HH)         // 1024 cols: [W1 | W2]
#define NEDGE (BB*EE)        // 200000 directed edge slots
#define NSEG  (BB*NN)        // 20000 segments per direction

// ---------------- scratch (static device globals; no allocation) -------------
__device__ float          g_pre[(size_t)MROWS * NTOT];     // 82 MB: X@[W1|W2]
__device__ __nv_bfloat16  g_Xb [(size_t)MROWS * FF];       // 20.5 MB bf16 X
__device__ __nv_bfloat16  g_Wb [(size_t)NTOT  * FF];       // 2 MB: [W1|W2]^T K-major
__device__ __nv_bfloat16  g_A1[(size_t)MROWS * HH];        // 20.5 MB
__device__ __nv_bfloat16  g_A2[(size_t)MROWS * HH];        // 20.5 MB
__device__ float          g_eij[NEDGE];
__device__ float          g_eji[NEDGE];
__device__ float          g_sums[2 * NSEG];                // [src sums | dst sums]

// ======================= PTX helpers (non-'a' safe) ===========================
__device__ __forceinline__ uint32_t smem_to_u32(const void* smem_ptr) {
    uint32_t addr;
    asm("{ .reg .u64 tmp; cvta.to.shared.u64 tmp, %1; cvt.u32.u64 %0, tmp; }"
        : "=r"(addr) : "l"(smem_ptr));
    return addr;
}

__device__ __forceinline__ void cp_async16(uint32_t dst, const void* src, int src_bytes) {
    asm volatile("cp.async.cg.shared.global [%0], [%1], 16, %2;"
        :: "r"(dst), "l"(src), "r"(src_bytes) : "memory");
}
#define CP_COMMIT() asm volatile("cp.async.commit_group;" ::: "memory")
#define CP_WAIT(n)  asm volatile("cp.async.wait_group %0;" :: "n"(n) : "memory")

__device__ __forceinline__ void ldmatrix_x4(
    uint32_t& r0, uint32_t& r1, uint32_t& r2, uint32_t& r3, uint32_t addr)
{
    asm volatile("ldmatrix.sync.aligned.m8n8.x4.shared.b16 {%0,%1,%2,%3}, [%4];"
        : "=r"(r0), "=r"(r1), "=r"(r2), "=r"(r3) : "r"(addr));
}

__device__ __forceinline__ void mma_bf16(
    float* c, uint32_t a0, uint32_t a1, uint32_t a2, uint32_t a3,
    uint32_t b0, uint32_t b1)
{
    asm volatile(
        "mma.sync.aligned.m16n8k16.row.col.f32.bf16.bf16.f32 "
        "{%0,%1,%2,%3}, {%4,%5,%6,%7}, {%8,%9}, {%0,%1,%2,%3};"
        : "+f"(c[0]), "+f"(c[1]), "+f"(c[2]), "+f"(c[3])
        : "r"(a0), "r"(a1), "r"(a2), "r"(a3), "r"(b0), "r"(b1));
}

// ---------------- kernel 0: zero segment sums --------------------------------
__global__ void zero_sums_kernel() {
    int i = blockIdx.x * blockDim.x + threadIdx.x;
    if (i < 2 * NSEG) g_sums[i] = 0.0f;
}

// ---------------- kernel A: convert X -> bf16 ---------------------------------
__global__ __launch_bounds__(256) void convX_kernel(const float* __restrict__ X) {
    size_t i = ((size_t)blockIdx.x * 256 + threadIdx.x) * 8;
    if (i >= (size_t)MROWS * FF) return;
    float4 a = *(const float4*)(X + i);
    float4 b = *(const float4*)(X + i + 4);
    __nv_bfloat162 o0 = __float22bfloat162_rn(make_float2(a.x, a.y));
    __nv_bfloat162 o1 = __float22bfloat162_rn(make_float2(a.z, a.w));
    __nv_bfloat162 o2 = __float22bfloat162_rn(make_float2(b.x, b.y));
    __nv_bfloat162 o3 = __float22bfloat162_rn(make_float2(b.z, b.w));
    uint4 o;
    o.x = *(uint32_t*)&o0; o.y = *(uint32_t*)&o1;
    o.z = *(uint32_t*)&o2; o.w = *(uint32_t*)&o3;
    *(uint4*)(g_Xb + i) = o;
}

// ---------------- kernel B: transpose [W1|W2] -> g_Wb[n][k] bf16 --------------
__global__ __launch_bounds__(256) void transW_kernel(
    const float* __restrict__ W1, const float* __restrict__ W2)
{
    __shared__ float t[32][33];
    int k0  = blockIdx.x * 32;        // 0..480
    int n0g = blockIdx.y * 32;        // 0..992 (over 1024)
    const float* W = (n0g < HH) ? W1 : W2;
    int n0 = n0g & (HH - 1);
    int tx = threadIdx.x, ty = threadIdx.y;  // (32, 8)
#pragma unroll
    for (int j = 0; j < 4; j++)
        t[ty + 8 * j][tx] = W[(size_t)(k0 + ty + 8 * j) * HH + n0 + tx];
    __syncthreads();
#pragma unroll
    for (int j = 0; j < 4; j++)
        g_Wb[(size_t)(n0g + ty + 8 * j) * FF + k0 + tx] =
            __float2bfloat16(t[tx][ty + 8 * j]);
}

// ---------------- kernel 1: bf16 HMMA GEMM (mma.sync m16n8k16) ----------------
// C[20000 x 1024] = Xb[20000 x 512] @ Wb^T   (Wb is [1024 n][512 k], K-major)
// CTA tile 128x128, BK=32, double-buffered cp.async. 8 warps = 4(m) x 2(n),
// warp tile 32x64: 2 m-frags x 8 n-frags = 16 HMMA per k16-step.
#define BK   32
#define LDS_ ((BK) + 8)          // bf16 elements per smem row (pad 16B)

__global__ __launch_bounds__(256) void gemm_mma_kernel()
{
    __shared__ __align__(16) __nv_bfloat16 sA[2][128][LDS_];
    __shared__ __align__(16) __nv_bfloat16 sB[2][128][LDS_];

    const int tid  = threadIdx.x;
    const int wid  = tid >> 5;
    const int lane = tid & 31;

    const int m0 = blockIdx.y * 128;
    const int n0 = blockIdx.x * 128;

    const int warp_m = wid >> 1;            // 0..3  -> 32 rows each
    const int warp_n = wid & 1;             // 0..1  -> 64 cols each

    // cp.async load indices (A: 128 rows x 32 cols = 512 x 16B; same for B)
    const int lrow = (tid * 2) >> 3;        // chunk pairs: each thread does 2 chunks
    // chunk id c = tid + j*256; row = c>>2; slice = c&3
    float acc[2][8][4];
#pragma unroll
    for (int i = 0; i < 2; i++)
#pragma unroll
        for (int j = 0; j < 8; j++)
#pragma unroll
            for (int q = 0; q < 4; q++) acc[i][j][q] = 0.0f;
    (void)lrow;

    const uint32_t sA_u = smem_to_u32(&sA[0][0][0]);
    const uint32_t sB_u = smem_to_u32(&sB[0][0][0]);
    const uint32_t bufA_stride = 128 * LDS_ * 2;   // bytes per A buffer
    const uint32_t bufB_stride = 128 * LDS_ * 2;

    auto load_tiles = [&](int it, int buf) {
        int k0 = it * BK;
#pragma unroll
        for (int j = 0; j < 2; j++) {
            int c   = tid + j * 256;       // 0..511
            int row = c >> 2;              // 0..127
            int sl  = c & 3;               // 16B slice (8 bf16)
            // A
            int gm = m0 + row;
            uint32_t dA = sA_u + buf * bufA_stride + (uint32_t)(row * LDS_ + sl * 8) * 2;
            cp_async16(dA, g_Xb + (size_t)gm * FF + k0 + sl * 8,
                       (gm < MROWS) ? 16 : 0);
            // B
            uint32_t dB = sB_u + buf * bufB_stride + (uint32_t)(row * LDS_ + sl * 8) * 2;
            cp_async16(dB, g_Wb + (size_t)(n0 + row) * FF + k0 + sl * 8, 16);
        }
        CP_COMMIT();
    };

    load_tiles(0, 0);

    const int NIT = FF / BK;   // 16
#pragma unroll 1
    for (int it = 0; it < NIT; ++it) {
        int buf = it & 1;
        if (it + 1 < NIT) load_tiles(it + 1, (it + 1) & 1);
        if (it + 1 < NIT) { CP_WAIT(1); } else { CP_WAIT(0); }
        __syncthreads();

#pragma unroll
        for (int ks = 0; ks < BK; ks += 16) {
            // A fragments: 2 m-tiles (m16 each)
            uint32_t a[2][4];
#pragma unroll
            for (int tm = 0; tm < 2; tm++) {
                int r = warp_m * 32 + tm * 16 + (lane & 15);
                int kk = ks + (lane >> 4) * 8;
                uint32_t addr = sA_u + buf * bufA_stride + (uint32_t)(r * LDS_ + kk) * 2;
                ldmatrix_x4(a[tm][0], a[tm][1], a[tm][2], a[tm][3], addr);
            }
            // B fragments: 8 n-tiles, loaded 2 at a time with x4
            uint32_t b[8][2];
#pragma unroll
            for (int tp = 0; tp < 4; tp++) {
                // lanes 0-7: n-tile(2tp) k-lo, 8-15: n-tile(2tp) k-hi,
                // 16-23: n-tile(2tp+1) k-lo, 24-31: n-tile(2tp+1) k-hi
                int nrow = warp_n * 64 + tp * 16 + ((lane >> 4) * 8) + (lane & 7);
                int kk   = ks + (((lane >> 3) & 1) * 8);
                uint32_t addr = sB_u + buf * bufB_stride + (uint32_t)(nrow * LDS_ + kk) * 2;
                ldmatrix_x4(b[2*tp][0], b[2*tp][1], b[2*tp+1][0], b[2*tp+1][1], addr);
            }
#pragma unroll
            for (int tm = 0; tm < 2; tm++)
#pragma unroll
                for (int tn = 0; tn < 8; tn++)
                    mma_bf16(acc[tm][tn], a[tm][0], a[tm][1], a[tm][2], a[tm][3],
                             b[tn][0], b[tn][1]);
        }
        __syncthreads();
    }

    // Epilogue: write fp32 accumulators to g_pre
    // c frag mapping: c0,c1 -> (r = lane>>2, col = (lane&3)*2 +0/1); c2,c3 -> r+8
    const int qrow = lane >> 2;
    const int qcol = (lane & 3) * 2;
#pragma unroll
    for (int tm = 0; tm < 2; tm++) {
        int mb = m0 + warp_m * 32 + tm * 16;
#pragma unroll
        for (int tn = 0; tn < 8; tn++) {
            int gcol = n0 + warp_n * 64 + tn * 8 + qcol;
            int r0 = mb + qrow;
            int r1 = mb + qrow + 8;
            if (r0 < MROWS)
                *(float2*)(g_pre + (size_t)r0 * NTOT + gcol) =
                    make_float2(acc[tm][tn][0], acc[tm][tn][1]);
            if (r1 < MROWS)
                *(float2*)(g_pre + (size_t)r1 * NTOT + gcol) =
                    make_float2(acc[tm][tn][2], acc[tm][tn][3]);
        }
    }
}

// ---------------- kernel 2: LayerNorm per row-half, write bf16 ---------------
__global__ __launch_bounds__(256) void ln_kernel(
    const float* __restrict__ b1, const float* __restrict__ g1, const float* __restrict__ bb1,
    const float* __restrict__ b2, const float* __restrict__ g2, const float* __restrict__ bb2)
{
    int row  = blockIdx.x;          // 0..19999
    int half = blockIdx.y;          // 0: W1 path, 1: W2 path
    const float* p   = g_pre + (size_t)row * NTOT + half * HH;
    const float* bv  = half ? b2  : b1;
    const float* gv  = half ? g2  : g1;
    const float* bbv = half ? bb2 : bb1;

    int t = threadIdx.x;
    float v0 = p[t]       + bv[t];
    float v1 = p[t + 256] + bv[t + 256];

    float s  = v0 + v1;
    float sq = v0 * v0 + v1 * v1;
#pragma unroll
    for (int o = 16; o; o >>= 1) {
        s  += __shfl_xor_sync(0xffffffffu, s,  o);
        sq += __shfl_xor_sync(0xffffffffu, sq, o);
    }
    __shared__ float red[2][8];
    int w = t >> 5, l = t & 31;
    if (l == 0) { red[0][w] = s; red[1][w] = sq; }
    __syncthreads();
    float S = 0.f, SQ = 0.f;
#pragma unroll
    for (int i = 0; i < 8; i++) { S += red[0][i]; SQ += red[1][i]; }

    float mu  = S * (1.0f / HH);
    float var = SQ * (1.0f / HH) - mu * mu;
    float rs  = rsqrtf(var + 1e-5f);

    __nv_bfloat16* Aout = (half ? g_A2 : g_A1) + (size_t)row * HH;
    Aout[t]       = __float2bfloat16((v0 - mu) * rs * gv[t]       + bbv[t]);
    Aout[t + 256] = __float2bfloat16((v1 - mu) * rs * gv[t + 256] + bbv[t + 256]);
}

// ---------------- kernel 3: warp-per-edge scoring + segment sums -------------
__device__ __forceinline__ void bf8_to_f(uint4 u, float* f) {
    const __nv_bfloat162* p = (const __nv_bfloat162*)&u;
#pragma unroll
    for (int i = 0; i < 4; i++) {
        float2 t = __bfloat1622float2(p[i]);
        f[2 * i]     = t.x;
        f[2 * i + 1] = t.y;
    }
}

__global__ __launch_bounds__(256) void edge_kernel(
    const int* __restrict__ ei,
    const float* __restrict__ W3,
    const float* __restrict__ W4,
    const float* __restrict__ b4)
{
    int gw   = (blockIdx.x * 256 + threadIdx.x) >> 5;
    int lane = threadIdx.x & 31;
    if (gw >= NEDGE) return;
    int b = gw / EE;
    int e = gw - b * EE;

    int src = ei[(size_t)b * 2 * EE + e];
    int dst = ei[(size_t)b * 2 * EE + EE + e];

    const __nv_bfloat16* a1s = g_A1 + ((size_t)b * NN + src) * HH;
    const __nv_bfloat16* a2s = g_A2 + ((size_t)b * NN + src) * HH;
    const __nv_bfloat16* a1d = g_A1 + ((size_t)b * NN + dst) * HH;
    const __nv_bfloat16* a2d = g_A2 + ((size_t)b * NN + dst) * HH;

    float s1 = 0.f, s2 = 0.f;
#pragma unroll
    for (int i = 0; i < 2; i++) {
        int off = (i * 32 + lane) * 8;
        float x1s[8], x2s[8], x1d[8], x2d[8];
        bf8_to_f(*(const uint4*)(a1s + off), x1s);
        bf8_to_f(*(const uint4*)(a2d + off), x2d);
        bf8_to_f(*(const uint4*)(a1d + off), x1d);
        bf8_to_f(*(const uint4*)(a2s + off), x2s);
        float4 wa = *(const float4*)(W3 + off);
        float4 wb = *(const float4*)(W3 + off + 4);
        float w[8] = {wa.x, wa.y, wa.z, wa.w, wb.x, wb.y, wb.z, wb.w};
#pragma unroll
        for (int j = 0; j < 8; j++) {
            s1 = fmaf(fmaxf(x1s[j] + x2d[j], 0.f), w[j], s1);
            s2 = fmaf(fmaxf(x1d[j] + x2s[j], 0.f), w[j], s2);
        }
    }
#pragma unroll
    for (int o = 16; o; o >>= 1) {
        s1 += __shfl_xor_sync(0xffffffffu, s1, o);
        s2 += __shfl_xor_sync(0xffffffffu, s2, o);
    }
    if (lane == 0) {
        float d  = s1 - s2;                 // b3 cancels in Zij - Zji
        float w4 = W4[0], bb = b4[0];
        float vij = fmaxf(fmaf( d, w4, bb), 0.f);
        float vji = fmaxf(fmaf(-d, w4, bb), 0.f);
        float pi = expf(vij);               // max-subtraction removable: exact ratio
        float pj = expf(vji);
        g_eij[(size_t)b * EE + e] = pi;
        g_eji[(size_t)b * EE + e] = pj;
        atomicAdd(&g_sums[b * NN + src], pi);
        atomicAdd(&g_sums[NSEG + b * NN + dst], pj);
    }
}

// ---------------- kernel 4: normalize + write output -------------------------
__global__ __launch_bounds__(256) void norm_kernel(
    const int* __restrict__ ei,
    float* __restrict__ out)
{
    int i = blockIdx.x * 256 + threadIdx.x;
    if (i >= NEDGE) return;
    int b = i / EE;
    int e = i - b * EE;
    int src = ei[(size_t)b * 2 * EE + e];
    int dst = ei[(size_t)b * 2 * EE + EE + e];
    out[i]         = g_eij[i] / g_sums[b * NN + src];
    out[NEDGE + i] = g_eji[i] / g_sums[NSEG + b * NN + dst];
}

// ---------------- launcher ---------------------------------------------------
extern "C" void kernel_launch(void* const* d_in, const int* in_sizes, int n_in,
                              void* d_out, int out_size)
{
    int idx = 0;
    const float* X  = (const float*)d_in[idx++];   // node_features
    const int*   EI = (const int*)  d_in[idx++];   // edge_index
    if (idx < n_in && in_sizes[idx] == 1) idx++;   // num_nodes scalar (if present)
    const float* W1  = (const float*)d_in[idx++];
    const float* b1  = (const float*)d_in[idx++];
    const float* g1  = (const float*)d_in[idx++];
    const float* bb1 = (const float*)d_in[idx++];
    const float* W2  = (const float*)d_in[idx++];
    const float* b2  = (const float*)d_in[idx++];
    const float* g2  = (const float*)d_in[idx++];
    const float* bb2 = (const float*)d_in[idx++];
    const float* W3  = (const float*)d_in[idx++];
    idx++;                                          // b3 (cancels)
    const float* W4  = (const float*)d_in[idx++];
    const float* b4  = (const float*)d_in[idx++];

    float* out = (float*)d_out;

    zero_sums_kernel<<<(2 * NSEG + 255) / 256, 256>>>();

    convX_kernel<<<(int)(((size_t)MROWS * FF / 8 + 255) / 256), 256>>>(X);

    dim3 tgrid(FF / 32, NTOT / 32);
    transW_kernel<<<tgrid, dim3(32, 8)>>>(W1, W2);

    dim3 ggrid(NTOT / 128, (MROWS + 127) / 128);
    gemm_mma_kernel<<<ggrid, 256>>>();

    dim3 lgrid(MROWS, 2);
    ln_kernel<<<lgrid, 256>>>(b1, g1, bb1, b2, g2, bb2);

    int edge_blocks = (NEDGE * 32 + 255) / 256;
    edge_kernel<<<edge_blocks, 256>>>(EI, W3, W4, b4);

    norm_kernel<<<(NEDGE + 255) / 256, 256>>>(EI, out);
}

// round 5
// speedup vs baseline: 3.0470x; 1.1061x over previous
#include <cuda_runtime.h>
#include <cuda_bf16.h>
#include <cstdint>

// Problem constants
#define BB   2
#define NN   10000
#define EE   100000
#define FF   512
#define HH   512
#define MROWS (BB*NN)        // 20000 rows into the node GEMM
#define NTOT  (2*HH)         // 1024 cols: [W1 | W2]
#define NEDGE (BB*EE)        // 200000 directed edge slots
#define NSEG  (BB*NN)        // 20000 segments per direction

// ---------------- scratch (static device globals; no allocation) -------------
__device__ __nv_bfloat16  g_preb[(size_t)MROWS * NTOT];    // 41 MB: X@[W1|W2] bf16
__device__ __nv_bfloat16  g_Xb [(size_t)MROWS * FF];       // 20.5 MB bf16 X
__device__ __nv_bfloat16  g_Wb [(size_t)NTOT  * FF];       // 1 MB: [W1|W2]^T K-major
__device__ __nv_bfloat16  g_A1[(size_t)MROWS * HH];        // 20.5 MB
__device__ __nv_bfloat16  g_A2[(size_t)MROWS * HH];        // 20.5 MB
__device__ float          g_eij[NEDGE];
__device__ float          g_eji[NEDGE];
__device__ float          g_sums[2 * NSEG];                // [src sums | dst sums]

// ======================= PTX helpers (non-'a' safe) ===========================
__device__ __forceinline__ uint32_t smem_to_u32(const void* smem_ptr) {
    uint32_t addr;
    asm("{ .reg .u64 tmp; cvta.to.shared.u64 tmp, %1; cvt.u32.u64 %0, tmp; }"
        : "=r"(addr) : "l"(smem_ptr));
    return addr;
}

__device__ __forceinline__ void cp_async16(uint32_t dst, const void* src, int src_bytes) {
    asm volatile("cp.async.cg.shared.global [%0], [%1], 16, %2;"
        :: "r"(dst), "l"(src), "r"(src_bytes) : "memory");
}
#define CP_COMMIT() asm volatile("cp.async.commit_group;" ::: "memory")
#define CP_WAIT(n)  asm volatile("cp.async.wait_group %0;" :: "n"(n) : "memory")

__device__ __forceinline__ void ldmatrix_x4(
    uint32_t& r0, uint32_t& r1, uint32_t& r2, uint32_t& r3, uint32_t addr)
{
    asm volatile("ldmatrix.sync.aligned.m8n8.x4.shared.b16 {%0,%1,%2,%3}, [%4];"
        : "=r"(r0), "=r"(r1), "=r"(r2), "=r"(r3) : "r"(addr));
}

__device__ __forceinline__ void mma_bf16(
    float* c, uint32_t a0, uint32_t a1, uint32_t a2, uint32_t a3,
    uint32_t b0, uint32_t b1)
{
    asm volatile(
        "mma.sync.aligned.m16n8k16.row.col.f32.bf16.bf16.f32 "
        "{%0,%1,%2,%3}, {%4,%5,%6,%7}, {%8,%9}, {%0,%1,%2,%3};"
        : "+f"(c[0]), "+f"(c[1]), "+f"(c[2]), "+f"(c[3])
        : "r"(a0), "r"(a1), "r"(a2), "r"(a3), "r"(b0), "r"(b1));
}

// ---------------- kernel 0: zero segment sums --------------------------------
__global__ void zero_sums_kernel() {
    int i = blockIdx.x * blockDim.x + threadIdx.x;
    if (i < 2 * NSEG) g_sums[i] = 0.0f;
}

// ---------------- kernel A: convert X -> bf16 ---------------------------------
__global__ __launch_bounds__(256) void convX_kernel(const float* __restrict__ X) {
    size_t i = ((size_t)blockIdx.x * 256 + threadIdx.x) * 8;
    if (i >= (size_t)MROWS * FF) return;
    float4 a = *(const float4*)(X + i);
    float4 b = *(const float4*)(X + i + 4);
    __nv_bfloat162 o0 = __float22bfloat162_rn(make_float2(a.x, a.y));
    __nv_bfloat162 o1 = __float22bfloat162_rn(make_float2(a.z, a.w));
    __nv_bfloat162 o2 = __float22bfloat162_rn(make_float2(b.x, b.y));
    __nv_bfloat162 o3 = __float22bfloat162_rn(make_float2(b.z, b.w));
    uint4 o;
    o.x = *(uint32_t*)&o0; o.y = *(uint32_t*)&o1;
    o.z = *(uint32_t*)&o2; o.w = *(uint32_t*)&o3;
    *(uint4*)(g_Xb + i) = o;
}

// ---------------- kernel B: transpose [W1|W2] -> g_Wb[n][k] bf16 --------------
__global__ __launch_bounds__(256) void transW_kernel(
    const float* __restrict__ W1, const float* __restrict__ W2)
{
    __shared__ float t[32][33];
    int k0  = blockIdx.x * 32;        // 0..480
    int n0g = blockIdx.y * 32;        // 0..992 (over 1024)
    const float* W = (n0g < HH) ? W1 : W2;
    int n0 = n0g & (HH - 1);
    int tx = threadIdx.x, ty = threadIdx.y;  // (32, 8)
#pragma unroll
    for (int j = 0; j < 4; j++)
        t[ty + 8 * j][tx] = W[(size_t)(k0 + ty + 8 * j) * HH + n0 + tx];
    __syncthreads();
#pragma unroll
    for (int j = 0; j < 4; j++)
        g_Wb[(size_t)(n0g + ty + 8 * j) * FF + k0 + tx] =
            __float2bfloat16(t[tx][ty + 8 * j]);
}

// ---------------- kernel 1: bf16 HMMA GEMM (mma.sync m16n8k16) ----------------
// C[20000 x 1024] = Xb[20000 x 512] @ Wb^T   (Wb is [1024 n][512 k], K-major)
// CTA tile 128x128, BK=64, 3-stage cp.async pipeline. 8 warps = 4(m) x 2(n),
// warp tile 32x64: 2 m-frags x 8 n-frags = 16 HMMA per k16-step.
#define BK    64
#define LDS_  ((BK) + 8)          // 72 bf16 per smem row (144B, 16B aligned)
#define NSTG  3
#define TILE_BYTES   (128 * LDS_ * 2)              // per matrix per stage: 18432B
#define STAGE_BYTES  (2 * TILE_BYTES)              // A+B per stage: 36864B
#define GEMM_SMEM    (NSTG * STAGE_BYTES)          // 110592B

__global__ __launch_bounds__(256) void gemm_mma_kernel()
{
    extern __shared__ __align__(16) char smem_raw[];
    const uint32_t sbase = smem_to_u32(smem_raw);

    const int tid  = threadIdx.x;
    const int wid  = tid >> 5;
    const int lane = tid & 31;

    const int m0 = blockIdx.y * 128;
    const int n0 = blockIdx.x * 128;

    const int warp_m = wid >> 1;            // 0..3  -> 32 rows each
    const int warp_n = wid & 1;             // 0..1  -> 64 cols each

    float acc[2][8][4];
#pragma unroll
    for (int i = 0; i < 2; i++)
#pragma unroll
        for (int j = 0; j < 8; j++)
#pragma unroll
            for (int q = 0; q < 4; q++) acc[i][j][q] = 0.0f;

    auto stageA = [&](int s) { return sbase + (uint32_t)s * STAGE_BYTES; };
    auto stageB = [&](int s) { return sbase + (uint32_t)s * STAGE_BYTES + TILE_BYTES; };

    // per-tile: A = 128 rows x 64 bf16 = 128 rows x 8 slices(16B) = 1024 chunks
    auto load_tiles = [&](int it, int s) {
        int k0 = it * BK;
        uint32_t aA = stageA(s), aB = stageB(s);
#pragma unroll
        for (int j = 0; j < 4; j++) {
            int c   = tid + j * 256;       // 0..1023
            int row = c >> 3;              // 0..127
            int sl  = c & 7;               // 16B slice (8 bf16)
            int gm  = m0 + row;
            uint32_t off = (uint32_t)(row * LDS_ + sl * 8) * 2;
            cp_async16(aA + off, g_Xb + (size_t)gm * FF + k0 + sl * 8,
                       (gm < MROWS) ? 16 : 0);
            cp_async16(aB + off, g_Wb + (size_t)(n0 + row) * FF + k0 + sl * 8, 16);
        }
        CP_COMMIT();
    };

    const int NIT = FF / BK;   // 8
    load_tiles(0, 0);
    load_tiles(1, 1);

#pragma unroll 1
    for (int it = 0; it < NIT; ++it) {
        int s = it % NSTG;
        if (it + 2 < NIT) { load_tiles(it + 2, (it + 2) % NSTG); CP_WAIT(2); }
        else if (it + 1 < NIT) { CP_WAIT(1); }
        else { CP_WAIT(0); }
        __syncthreads();

        uint32_t aA = stageA(s), aB = stageB(s);
#pragma unroll
        for (int ks = 0; ks < BK; ks += 16) {
            uint32_t a[2][4];
#pragma unroll
            for (int tm = 0; tm < 2; tm++) {
                int r  = warp_m * 32 + tm * 16 + (lane & 15);
                int kk = ks + (lane >> 4) * 8;
                ldmatrix_x4(a[tm][0], a[tm][1], a[tm][2], a[tm][3],
                            aA + (uint32_t)(r * LDS_ + kk) * 2);
            }
            uint32_t b[8][2];
#pragma unroll
            for (int tp = 0; tp < 4; tp++) {
                int nrow = warp_n * 64 + tp * 16 + ((lane >> 4) * 8) + (lane & 7);
                int kk   = ks + (((lane >> 3) & 1) * 8);
                ldmatrix_x4(b[2*tp][0], b[2*tp][1], b[2*tp+1][0], b[2*tp+1][1],
                            aB + (uint32_t)(nrow * LDS_ + kk) * 2);
            }
#pragma unroll
            for (int tm = 0; tm < 2; tm++)
#pragma unroll
                for (int tn = 0; tn < 8; tn++)
                    mma_bf16(acc[tm][tn], a[tm][0], a[tm][1], a[tm][2], a[tm][3],
                             b[tn][0], b[tn][1]);
        }
        __syncthreads();
    }

    // Epilogue: write bf16 to g_preb
    const int qrow = lane >> 2;
    const int qcol = (lane & 3) * 2;
#pragma unroll
    for (int tm = 0; tm < 2; tm++) {
        int mb = m0 + warp_m * 32 + tm * 16;
#pragma unroll
        for (int tn = 0; tn < 8; tn++) {
            int gcol = n0 + warp_n * 64 + tn * 8 + qcol;
            int r0 = mb + qrow;
            int r1 = mb + qrow + 8;
            __nv_bfloat162 p0 = __float22bfloat162_rn(
                make_float2(acc[tm][tn][0], acc[tm][tn][1]));
            __nv_bfloat162 p1 = __float22bfloat162_rn(
                make_float2(acc[tm][tn][2], acc[tm][tn][3]));
            if (r0 < MROWS)
                *(__nv_bfloat162*)(g_preb + (size_t)r0 * NTOT + gcol) = p0;
            if (r1 < MROWS)
                *(__nv_bfloat162*)(g_preb + (size_t)r1 * NTOT + gcol) = p1;
        }
    }
}

// ---------------- kernel 2: LayerNorm per row-half, bf16 in/out --------------
__global__ __launch_bounds__(256) void ln_kernel(
    const float* __restrict__ b1, const float* __restrict__ g1, const float* __restrict__ bb1,
    const float* __restrict__ b2, const float* __restrict__ g2, const float* __restrict__ bb2)
{
    int row  = blockIdx.x;          // 0..19999
    int half = blockIdx.y;          // 0: W1 path, 1: W2 path
    const __nv_bfloat16* p = g_preb + (size_t)row * NTOT + half * HH;
    const float* bv  = half ? b2  : b1;
    const float* gv  = half ? g2  : g1;
    const float* bbv = half ? bb2 : bb1;

    int t = threadIdx.x;            // handles elems 2t, 2t+1
    float2 raw = __bfloat1622float2(*(const __nv_bfloat162*)(p + 2 * t));
    float2 bb2v = *(const float2*)(bv + 2 * t);
    float v0 = raw.x + bb2v.x;
    float v1 = raw.y + bb2v.y;

    float s  = v0 + v1;
    float sq = v0 * v0 + v1 * v1;
#pragma unroll
    for (int o = 16; o; o >>= 1) {
        s  += __shfl_xor_sync(0xffffffffu, s,  o);
        sq += __shfl_xor_sync(0xffffffffu, sq, o);
    }
    __shared__ float red[2][8];
    int w = t >> 5, l = t & 31;
    if (l == 0) { red[0][w] = s; red[1][w] = sq; }
    __syncthreads();
    float S = 0.f, SQ = 0.f;
#pragma unroll
    for (int i = 0; i < 8; i++) { S += red[0][i]; SQ += red[1][i]; }

    float mu  = S * (1.0f / HH);
    float var = SQ * (1.0f / HH) - mu * mu;
    float rs  = rsqrtf(var + 1e-5f);

    float2 gvv  = *(const float2*)(gv + 2 * t);
    float2 bbvv = *(const float2*)(bbv + 2 * t);
    __nv_bfloat16* Aout = (half ? g_A2 : g_A1) + (size_t)row * HH;
    float o0 = (v0 - mu) * rs * gvv.x + bbvv.x;
    float o1 = (v1 - mu) * rs * gvv.y + bbvv.y;
    *(__nv_bfloat162*)(Aout + 2 * t) = __float22bfloat162_rn(make_float2(o0, o1));
}

// ---------------- kernel 3: warp-per-edge scoring + segment sums -------------
__device__ __forceinline__ void bf8_to_f(uint4 u, float* f) {
    const __nv_bfloat162* p = (const __nv_bfloat162*)&u;
#pragma unroll
    for (int i = 0; i < 4; i++) {
        float2 t = __bfloat1622float2(p[i]);
        f[2 * i]     = t.x;
        f[2 * i + 1] = t.y;
    }
}

__global__ __launch_bounds__(256) void edge_kernel(
    const int* __restrict__ ei,
    const float* __restrict__ W3,
    const float* __restrict__ W4,
    const float* __restrict__ b4)
{
    int gw   = (blockIdx.x * 256 + threadIdx.x) >> 5;
    int lane = threadIdx.x & 31;
    if (gw >= NEDGE) return;
    int b = gw / EE;
    int e = gw - b * EE;

    int src = ei[(size_t)b * 2 * EE + e];
    int dst = ei[(size_t)b * 2 * EE + EE + e];

    const __nv_bfloat16* a1s = g_A1 + ((size_t)b * NN + src) * HH;
    const __nv_bfloat16* a2s = g_A2 + ((size_t)b * NN + src) * HH;
    const __nv_bfloat16* a1d = g_A1 + ((size_t)b * NN + dst) * HH;
    const __nv_bfloat16* a2d = g_A2 + ((size_t)b * NN + dst) * HH;

    float s1 = 0.f, s2 = 0.f;
#pragma unroll
    for (int i = 0; i < 2; i++) {
        int off = (i * 32 + lane) * 8;
        float x1s[8], x2s[8], x1d[8], x2d[8];
        bf8_to_f(*(const uint4*)(a1s + off), x1s);
        bf8_to_f(*(const uint4*)(a2d + off), x2d);
        bf8_to_f(*(const uint4*)(a1d + off), x1d);
        bf8_to_f(*(const uint4*)(a2s + off), x2s);
        float4 wa = *(const float4*)(W3 + off);
        float4 wb = *(const float4*)(W3 + off + 4);
        float w[8] = {wa.x, wa.y, wa.z, wa.w, wb.x, wb.y, wb.z, wb.w};
#pragma unroll
        for (int j = 0; j < 8; j++) {
            s1 = fmaf(fmaxf(x1s[j] + x2d[j], 0.f), w[j], s1);
            s2 = fmaf(fmaxf(x1d[j] + x2s[j], 0.f), w[j], s2);
        }
    }
#pragma unroll
    for (int o = 16; o; o >>= 1) {
        s1 += __shfl_xor_sync(0xffffffffu, s1, o);
        s2 += __shfl_xor_sync(0xffffffffu, s2, o);
    }
    if (lane == 0) {
        float d  = s1 - s2;                 // b3 cancels in Zij - Zji
        float w4 = W4[0], bb = b4[0];
        float vij = fmaxf(fmaf( d, w4, bb), 0.f);
        float vji = fmaxf(fmaf(-d, w4, bb), 0.f);
        float pi = expf(vij);               // max-subtraction removable: exact ratio
        float pj = expf(vji);
        g_eij[(size_t)b * EE + e] = pi;
        g_eji[(size_t)b * EE + e] = pj;
        atomicAdd(&g_sums[b * NN + src], pi);
        atomicAdd(&g_sums[NSEG + b * NN + dst], pj);
    }
}

// ---------------- kernel 4: normalize + write output -------------------------
__global__ __launch_bounds__(256) void norm_kernel(
    const int* __restrict__ ei,
    float* __restrict__ out)
{
    int i = blockIdx.x * 256 + threadIdx.x;
    if (i >= NEDGE) return;
    int b = i / EE;
    int e = i - b * EE;
    int src = ei[(size_t)b * 2 * EE + e];
    int dst = ei[(size_t)b * 2 * EE + EE + e];
    out[i]         = g_eij[i] / g_sums[b * NN + src];
    out[NEDGE + i] = g_eji[i] / g_sums[NSEG + b * NN + dst];
}

// ---------------- launcher ---------------------------------------------------
extern "C" void kernel_launch(void* const* d_in, const int* in_sizes, int n_in,
                              void* d_out, int out_size)
{
    int idx = 0;
    const float* X  = (const float*)d_in[idx++];   // node_features
    const int*   EI = (const int*)  d_in[idx++];   // edge_index
    if (idx < n_in && in_sizes[idx] == 1) idx++;   // num_nodes scalar (if present)
    const float* W1  = (const float*)d_in[idx++];
    const float* b1  = (const float*)d_in[idx++];
    const float* g1  = (const float*)d_in[idx++];
    const float* bb1 = (const float*)d_in[idx++];
    const float* W2  = (const float*)d_in[idx++];
    const float* b2  = (const float*)d_in[idx++];
    const float* g2  = (const float*)d_in[idx++];
    const float* bb2 = (const float*)d_in[idx++];
    const float* W3  = (const float*)d_in[idx++];
    idx++;                                          // b3 (cancels)
    const float* W4  = (const float*)d_in[idx++];
    const float* b4  = (const float*)d_in[idx++];

    float* out = (float*)d_out;

    zero_sums_kernel<<<(2 * NSEG + 255) / 256, 256>>>();

    convX_kernel<<<(int)(((size_t)MROWS * FF / 8 + 255) / 256), 256>>>(X);

    dim3 tgrid(FF / 32, NTOT / 32);
    transW_kernel<<<tgrid, dim3(32, 8)>>>(W1, W2);

    cudaFuncSetAttribute(gemm_mma_kernel,
                         cudaFuncAttributeMaxDynamicSharedMemorySize, GEMM_SMEM);
    dim3 ggrid(NTOT / 128, (MROWS + 127) / 128);
    gemm_mma_kernel<<<ggrid, 256, GEMM_SMEM>>>();

    dim3 lgrid(MROWS, 2);
    ln_kernel<<<lgrid, 256>>>(b1, g1, bb1, b2, g2, bb2);

    int edge_blocks = (NEDGE * 32 + 255) / 256;
    edge_kernel<<<edge_blocks, 256>>>(EI, W3, W4, b4);

    norm_kernel<<<(NEDGE + 255) / 256, 256>>>(EI, out);
}